// round 1
// baseline (speedup 1.0000x reference)
#include <cuda_runtime.h>
#include <math.h>
#include <stdint.h>

#define Bk   4
#define Lk   4096
#define Dk   512
#define DFFk 2048
#define NFk  2049          // rfft bins = L/2+1
#define KTOP 8
#define PI_D 3.14159265358979323846

// ---------------- scratch (static device globals; no allocation) ----------------
__device__ float  g_V    [Bk*Lk*Dk];
__device__ float  g_U    [2*Bk*NFk*Dk];   // [re block ; im block], rows = b*NF+f
__device__ float  g_FQ   [2*Bk*NFk*Dk];
__device__ float  g_FK   [2*Bk*NFk*Dk];
__device__ float2 g_S    [Bk*NFk];
__device__ float  g_corr [Bk*Lk];
__device__ int    g_delay[Bk*KTOP];
__device__ float  g_p    [Bk*KTOP];
__device__ float  g_attn [Bk*Lk*Dk];
__device__ float  g_h    [Bk*Lk*Dk];
__device__ float  g_S1   [Bk*Lk*Dk];
__device__ float  g_hid  [Bk*Lk*DFFk];
__device__ float  g_h2   [Bk*Lk*Dk];
__device__ float2 g_tw   [Lk/2];          // exp(-2*pi*i*k/L)

// ---------------- twiddle init (deterministic, every launch) ----------------
__global__ void init_tw_kernel() {
    int k = blockIdx.x * blockDim.x + threadIdx.x;
    if (k < Lk/2) {
        double ang = -2.0 * PI_D * (double)k / (double)Lk;
        g_tw[k] = make_float2((float)cos(ang), (float)sin(ang));
    }
}

// ---------------- in-smem iterative radix-2 FFT (input already bit-reversed) ----------------
__device__ __forceinline__ void fft_core(float2* s) {
    for (int len = 2; len <= Lk; len <<= 1) {
        int half = len >> 1;
        int lh   = __ffs(half) - 1;
        int tws  = Lk / len;
        for (int j = threadIdx.x; j < Lk/2; j += blockDim.x) {
            int k  = j & (half - 1);
            int g  = j >> lh;
            int i0 = g * len + k;
            int i1 = i0 + half;
            float2 w = g_tw[k * tws];
            float2 a = s[i0], b = s[i1];
            float tre = w.x * b.x - w.y * b.y;
            float tim = w.x * b.y + w.y * b.x;
            s[i1] = make_float2(a.x - tre, a.y - tim);
            s[i0] = make_float2(a.x + tre, a.y + tim);
        }
        __syncthreads();
    }
}

// Forward FFT of x over time, two real channels packed per complex FFT.
// Writes U (stacked re/im spectrum), rows r = b*NF+f, cols d.
__global__ void fft_x_kernel(const float* __restrict__ x) {
    __shared__ float2 s[Lk];
    int b  = blockIdx.x;
    int pr = blockIdx.y;
    int d0 = 2 * pr, d1 = d0 + 1;
    const float* xb = x + (size_t)b * Lk * Dk;
    for (int t = threadIdx.x; t < Lk; t += blockDim.x) {
        int r = __brev((unsigned)t) >> (32 - 12);
        s[r] = make_float2(xb[(size_t)t * Dk + d0], xb[(size_t)t * Dk + d1]);
    }
    __syncthreads();
    fft_core(s);
    float* Ure = g_U;
    float* Uim = g_U + (size_t)Bk * NFk * Dk;
    for (int f = threadIdx.x; f <= Lk/2; f += blockDim.x) {
        float2 zf = s[f];
        float2 zn = s[(Lk - f) & (Lk - 1)];
        float are = 0.5f * (zf.x + zn.x);
        float aim = 0.5f * (zf.y - zn.y);
        float bre = 0.5f * (zf.y + zn.y);
        float bim = 0.5f * (zn.x - zf.x);
        size_t row = ((size_t)b * NFk + f) * Dk;
        Ure[row + d0] = are;  Uim[row + d0] = aim;
        Ure[row + d1] = bre;  Uim[row + d1] = bim;
    }
}

// S[b,f] = sum_d FQ[b,f,d] * conj(FK[b,f,d]), with exact f=0 bias correction.
__global__ void sreduce_kernel(const float* __restrict__ bq, const float* __restrict__ bk) {
    int row = blockIdx.x;                // b*NF + f
    int f   = row % NFk;
    const float* qre = g_FQ + (size_t)row * Dk;
    const float* qim = g_FQ + ((size_t)(Bk*NFk) + row) * Dk;
    const float* kre = g_FK + (size_t)row * Dk;
    const float* kim = g_FK + ((size_t)(Bk*NFk) + row) * Dk;
    float sre = 0.f, sim = 0.f;
    for (int d = threadIdx.x; d < Dk; d += blockDim.x) {
        float qr = qre[d], qi = qim[d], kr = kre[d], ki = kim[d];
        if (f == 0) { qr += (float)Lk * bq[d]; kr += (float)Lk * bk[d]; }
        sre += qr * kr + qi * ki;
        sim += qi * kr - qr * ki;
    }
    __shared__ float rre[128], rim[128];
    int tid = threadIdx.x;
    rre[tid] = sre; rim[tid] = sim;
    __syncthreads();
    for (int st = 64; st > 0; st >>= 1) {
        if (tid < st) { rre[tid] += rre[tid + st]; rim[tid] += rim[tid + st]; }
        __syncthreads();
    }
    if (tid == 0) g_S[row] = make_float2(rre[0], rim[0]);
}

// mean_corr = irfft(S)/D via conj trick through the forward FFT core.
__global__ void ifft_corr_kernel() {
    __shared__ float2 s[Lk];
    int b = blockIdx.x;
    for (int f = threadIdx.x; f < Lk; f += blockDim.x) {
        float2 v;
        if (f <= Lk/2) { float2 sf = g_S[b * NFk + f]; v = make_float2(sf.x, -sf.y); }
        else           { v = g_S[b * NFk + (Lk - f)]; }
        int r = __brev((unsigned)f) >> (32 - 12);
        s[r] = v;
    }
    __syncthreads();
    fft_core(s);
    float scale = 1.0f / ((float)Lk * (float)Dk);
    for (int t = threadIdx.x; t < Lk; t += blockDim.x)
        g_corr[b * Lk + t] = s[t].x * scale;
}

// top-8 (stable, descending, lower-index wins ties) + softmax
__global__ void topk_kernel() {
    int b = blockIdx.x;
    const float* c = g_corr + b * Lk;
    __shared__ float sv[256];
    __shared__ int   si[256];
    __shared__ int   ch_i[KTOP];
    __shared__ float ch_v[KTOP];
    int tid = threadIdx.x;
    for (int it = 0; it < KTOP; it++) {
        float bv = -3.402823e38f; int bi = 0x7fffffff;
        for (int t = tid; t < Lk; t += 256) {
            bool skip = false;
            for (int q = 0; q < it; q++) if (ch_i[q] == t) skip = true;
            if (skip) continue;
            float v = c[t];
            if (v > bv || (v == bv && t < bi)) { bv = v; bi = t; }
        }
        sv[tid] = bv; si[tid] = bi;
        __syncthreads();
        for (int st = 128; st > 0; st >>= 1) {
            if (tid < st) {
                if (sv[tid+st] > sv[tid] || (sv[tid+st] == sv[tid] && si[tid+st] < si[tid])) {
                    sv[tid] = sv[tid+st]; si[tid] = si[tid+st];
                }
            }
            __syncthreads();
        }
        if (tid == 0) { ch_i[it] = si[0]; ch_v[it] = sv[0]; }
        __syncthreads();
    }
    if (tid == 0) {
        float m = ch_v[0];
        for (int q = 1; q < KTOP; q++) m = fmaxf(m, ch_v[q]);
        float e[KTOP]; float sum = 0.f;
        for (int q = 0; q < KTOP; q++) { e[q] = expf(ch_v[q] - m); sum += e[q]; }
        for (int q = 0; q < KTOP; q++) {
            g_p[b*KTOP+q]     = e[q] / sum;
            g_delay[b*KTOP+q] = ch_i[q];
        }
    }
}

// attn[b,t,:] = sum_j p_j * V[b,(t+delay_j)%L,:]
__global__ void gather_kernel() {
    int bt = blockIdx.x;
    int b = bt >> 12, t = bt & (Lk - 1);
    __shared__ float pp[KTOP];
    __shared__ int   dd[KTOP];
    if (threadIdx.x < KTOP) {
        pp[threadIdx.x] = g_p[b*KTOP + threadIdx.x];
        dd[threadIdx.x] = g_delay[b*KTOP + threadIdx.x];
    }
    __syncthreads();
    int d = threadIdx.x * 4;
    float4 acc = make_float4(0.f, 0.f, 0.f, 0.f);
    #pragma unroll
    for (int j = 0; j < KTOP; j++) {
        int src = (t + dd[j]) & (Lk - 1);
        float4 v = *(const float4*)&g_V[(((size_t)b * Lk) + src) * Dk + d];
        acc.x += pp[j] * v.x; acc.y += pp[j] * v.y;
        acc.z += pp[j] * v.z; acc.w += pp[j] * v.w;
    }
    *(float4*)&g_attn[(size_t)bt * Dk + d] = acc;
}

// out = h - avgpool_same(h, 25)  (running-window per (b,d) column)
__global__ void pool_kernel(const float* __restrict__ h, float* __restrict__ out) {
    int b  = blockIdx.y;
    int t0 = blockIdx.x * 512;
    int d  = threadIdx.x;
    const float* hb = h   + (size_t)b * Lk * Dk + d;
    float*       ob = out + (size_t)b * Lk * Dk + d;
    float sum = 0.f;
    int lo = t0 - 12 < 0 ? 0 : t0 - 12;
    int hi = t0 + 12 > Lk - 1 ? Lk - 1 : t0 + 12;
    for (int t = lo; t <= hi; t++) sum += hb[(size_t)t * Dk];
    for (int t = t0; t < t0 + 512; t++) {
        int wlo = t - 12 < 0 ? 0 : t - 12;
        int whi = t + 12 > Lk - 1 ? Lk - 1 : t + 12;
        float cnt = (float)(whi - wlo + 1);
        ob[(size_t)t * Dk] = hb[(size_t)t * Dk] - sum / cnt;
        int add = t + 13; if (add < Lk)  sum += hb[(size_t)add * Dk];
        int rem = t - 12; if (rem >= 0)  sum -= hb[(size_t)rem * Dk];
    }
}

// ---------------- fp32 SGEMM: C = act(A@B + bias) + res ----------------
// 128x128 tile, BK=8, 256 threads, 8x8 microtile. N,K multiples of 128/8; M guarded.
template<bool RELU>
__global__ void __launch_bounds__(256) sgemm_kernel(
    const float* __restrict__ A, const float* __restrict__ B,
    const float* __restrict__ bias, const float* __restrict__ res,
    float* __restrict__ C, int M, int N, int K)
{
    __shared__ float As[8][128];
    __shared__ float Bs[8][128];
    const int bm  = blockIdx.y * 128;
    const int bn  = blockIdx.x * 128;
    const int tid = threadIdx.x;
    const int tr  = tid >> 4;
    const int tc  = tid & 15;
    const int arow = tid >> 1;
    const int acol = (tid & 1) * 4;
    const int brow = tid >> 5;
    const int bcol = (tid & 31) * 4;

    float acc[8][8];
    #pragma unroll
    for (int i = 0; i < 8; i++)
        #pragma unroll
        for (int j = 0; j < 8; j++) acc[i][j] = 0.f;

    const bool aval = (bm + arow) < M;
    const float* Aptr = A + (size_t)(bm + arow) * K + acol;
    const float* Bptr = B + (size_t)brow * N + bn + bcol;

    for (int k0 = 0; k0 < K; k0 += 8) {
        float4 av = aval ? *(const float4*)(Aptr + k0) : make_float4(0.f,0.f,0.f,0.f);
        float4 bv = *(const float4*)(Bptr + (size_t)k0 * N);
        As[acol+0][arow] = av.x;
        As[acol+1][arow] = av.y;
        As[acol+2][arow] = av.z;
        As[acol+3][arow] = av.w;
        *(float4*)&Bs[brow][bcol] = bv;
        __syncthreads();
        #pragma unroll
        for (int kk = 0; kk < 8; kk++) {
            float4 a0 = *(const float4*)&As[kk][tr*4];
            float4 a1 = *(const float4*)&As[kk][64 + tr*4];
            float4 b0 = *(const float4*)&Bs[kk][tc*4];
            float4 b1 = *(const float4*)&Bs[kk][64 + tc*4];
            float ar[8] = {a0.x,a0.y,a0.z,a0.w,a1.x,a1.y,a1.z,a1.w};
            float br[8] = {b0.x,b0.y,b0.z,b0.w,b1.x,b1.y,b1.z,b1.w};
            #pragma unroll
            for (int i = 0; i < 8; i++)
                #pragma unroll
                for (int j = 0; j < 8; j++)
                    acc[i][j] += ar[i] * br[j];
        }
        __syncthreads();
    }

    #pragma unroll
    for (int i = 0; i < 8; i++) {
        int row = bm + ((i < 4) ? tr*4 + i : 64 + tr*4 + (i - 4));
        if (row >= M) continue;
        #pragma unroll
        for (int jh = 0; jh < 2; jh++) {
            int col0 = bn + (jh == 0 ? tc*4 : 64 + tc*4);
            float4 v;
            float* vv = (float*)&v;
            #pragma unroll
            for (int j = 0; j < 4; j++) {
                float tvl = acc[i][jh*4 + j];
                int col = col0 + j;
                if (bias) tvl += bias[col];
                if (RELU) tvl = fmaxf(tvl, 0.f);
                if (res)  tvl += res[(size_t)row * N + col];
                vv[j] = tvl;
            }
            *(float4*)&C[(size_t)row * N + col0] = v;
        }
    }
}

// ---------------- launch ----------------
extern "C" void kernel_launch(void* const* d_in, const int* in_sizes, int n_in,
                              void* d_out, int out_size) {
    const float* x  = (const float*)d_in[0];
    const float* Wq = (const float*)d_in[1];
    const float* bq = (const float*)d_in[2];
    const float* Wk = (const float*)d_in[3];
    const float* bk = (const float*)d_in[4];
    const float* Wv = (const float*)d_in[5];
    const float* bv = (const float*)d_in[6];
    const float* Wo = (const float*)d_in[7];
    const float* bo = (const float*)d_in[8];
    const float* W1 = (const float*)d_in[9];
    const float* b1 = (const float*)d_in[10];
    const float* W2 = (const float*)d_in[11];
    const float* b2 = (const float*)d_in[12];
    float* out = (float*)d_out;

    float *pV, *pU, *pFQ, *pFK, *pattn, *ph, *pS1, *phid, *ph2;
    cudaGetSymbolAddress((void**)&pV,   g_V);
    cudaGetSymbolAddress((void**)&pU,   g_U);
    cudaGetSymbolAddress((void**)&pFQ,  g_FQ);
    cudaGetSymbolAddress((void**)&pFK,  g_FK);
    cudaGetSymbolAddress((void**)&pattn,g_attn);
    cudaGetSymbolAddress((void**)&ph,   g_h);
    cudaGetSymbolAddress((void**)&pS1,  g_S1);
    cudaGetSymbolAddress((void**)&phid, g_hid);
    cudaGetSymbolAddress((void**)&ph2,  g_h2);

    const int MR  = Bk * Lk;          // 16384
    const int MU  = 2 * Bk * NFk;     // 16392

    init_tw_kernel<<<(Lk/2 + 255)/256, 256>>>();

    // V = x@Wv + bv
    sgemm_kernel<false><<<dim3(Dk/128, MR/128), 256>>>(x, Wv, bv, nullptr, pV, MR, Dk, Dk);

    // spectrum of x
    fft_x_kernel<<<dim3(Bk, Dk/2), 512>>>(x);

    // FQ = U@Wq ; FK = U@Wk  (stacked re/im rows)
    sgemm_kernel<false><<<dim3(Dk/128, (MU + 127)/128), 256>>>(pU, Wq, nullptr, nullptr, pFQ, MU, Dk, Dk);
    sgemm_kernel<false><<<dim3(Dk/128, (MU + 127)/128), 256>>>(pU, Wk, nullptr, nullptr, pFK, MU, Dk, Dk);

    // S, mean_corr, top-k, gather
    sreduce_kernel<<<Bk * NFk, 128>>>(bq, bk);
    ifft_corr_kernel<<<Bk, 512>>>();
    topk_kernel<<<Bk, 256>>>();
    gather_kernel<<<Bk * Lk, 128>>>();

    // h = attn@Wo + bo + x
    sgemm_kernel<false><<<dim3(Dk/128, MR/128), 256>>>(pattn, Wo, bo, x, ph, MR, Dk, Dk);

    // S1 = h - avgpool(h)
    pool_kernel<<<dim3(Lk/512, Bk), 512>>>(ph, pS1);

    // hidden = relu(S1@W1 + b1)
    sgemm_kernel<true><<<dim3(DFFk/128, MR/128), 256>>>(pS1, W1, b1, nullptr, phid, MR, DFFk, Dk);

    // h2 = relu(hidden@W2 + b2) + S1
    sgemm_kernel<true><<<dim3(Dk/128, MR/128), 256>>>(phid, W2, b2, pS1, ph2, MR, Dk, DFFk);

    // out = h2 - avgpool(h2)
    pool_kernel<<<dim3(Lk/512, Bk), 512>>>(ph2, out);
}

// round 5
// speedup vs baseline: 1.6902x; 1.6902x over previous
#include <cuda_runtime.h>
#include <cuda_bf16.h>
#include <math.h>
#include <stdint.h>

#define Bk   4
#define Lk   4096
#define Dk   512
#define DFFk 2048
#define NFk  2049          // rfft bins = L/2+1
#define KTOP 8
#define PI_D 3.14159265358979323846

// ---------------- scratch (static device globals; no allocation) ----------------
__device__ float  g_V    [Bk*Lk*Dk];
__device__ float  g_U    [2*Bk*NFk*Dk];   // [re block ; im block], rows = b*NF+f
__device__ float  g_VU   [2*Bk*NFk*Dk];   // U @ G
__device__ float2 g_S    [Bk*NFk];
__device__ float  g_corr [Bk*Lk];
__device__ int    g_delay[Bk*KTOP];
__device__ float  g_p    [Bk*KTOP];
__device__ float  g_attn [Bk*Lk*Dk];
__device__ float  g_h    [Bk*Lk*Dk];
__device__ float  g_S1   [Bk*Lk*Dk];
__device__ float  g_hid  [Bk*Lk*DFFk];
__device__ float  g_h2   [Bk*Lk*Dk];
__device__ float2 g_tw   [Lk/2];          // exp(-2*pi*i*k/L)
__device__ float  g_G    [Dk*Dk];         // Wq @ Wk^T

// bf16 split weights ([N,K] layout for the mma B operand = W^T)
__device__ __nv_bfloat16 g_Wvt_h[Dk*Dk],  g_Wvt_l[Dk*Dk];
__device__ __nv_bfloat16 g_Wot_h[Dk*Dk],  g_Wot_l[Dk*Dk];
__device__ __nv_bfloat16 g_W1t_h[DFFk*Dk],g_W1t_l[DFFk*Dk];
__device__ __nv_bfloat16 g_W2t_h[Dk*DFFk],g_W2t_l[Dk*DFFk];
__device__ __nv_bfloat16 g_Wk_h [Dk*Dk],  g_Wk_l [Dk*Dk];   // Wk is already [N,K] for the G gemm
__device__ __nv_bfloat16 g_Gt_h [Dk*Dk],  g_Gt_l [Dk*Dk];

// ---------------- mma.sync bf16 GEMM (sm_80-compatible PTX, static smem) ----------------
// C = act(A @ Bt^T + bias) + res ; A fp32 [M,K]; Bt hi/lo bf16 [N,K].
// 3-term split: Ah*Bh + Ah*Bl + Al*Bh. CTA 128x128, BK=32, 256 thr, 8 warps of 32x64.
// Single smem stage (40KB static) + register prefetch of next stage.
#define ROWU 20                        // u32 per padded row (40 bf16)
#define TILE_U32 (128*ROWU)            // 2560

__device__ __forceinline__ void mma16816(float* c, const uint32_t* a,
                                         uint32_t b0, uint32_t b1) {
    asm volatile(
        "mma.sync.aligned.m16n8k16.row.col.f32.bf16.bf16.f32 "
        "{%0,%1,%2,%3}, {%4,%5,%6,%7}, {%8,%9}, {%0,%1,%2,%3};"
        : "+f"(c[0]), "+f"(c[1]), "+f"(c[2]), "+f"(c[3])
        : "r"(a[0]), "r"(a[1]), "r"(a[2]), "r"(a[3]), "r"(b0), "r"(b1));
}

template<bool RELU>
__global__ void __launch_bounds__(256, 1)
mmgemm_kernel(const float* __restrict__ A,
              const __nv_bfloat16* __restrict__ Bhi,
              const __nv_bfloat16* __restrict__ Blo,
              const float* __restrict__ bias,
              const float* __restrict__ res,
              float* __restrict__ C,
              int M, int N, int K)
{
    __shared__ uint32_t smem[4 * TILE_U32];   // 40KB static: Ah, Al, Bh, Bl
    uint32_t* sAh = smem;
    uint32_t* sAl = smem + TILE_U32;
    uint32_t* sBh = smem + 2 * TILE_U32;
    uint32_t* sBl = smem + 3 * TILE_U32;

    const int tid = threadIdx.x;
    const int bm  = blockIdx.y * 128;
    const int bn  = blockIdx.x * 128;
    const int w   = tid >> 5;            // warp 0..7
    const int l   = tid & 31;
    const int g   = l >> 2;              // group 0..7
    const int t   = l & 3;               // thread-in-group
    const int wm  = (w & 3) * 32;        // warp m offset (4 warps down)
    const int wn  = (w >> 2) * 64;       // warp n offset (2 warps across)

    float acc[2][8][4];
    #pragma unroll
    for (int i = 0; i < 2; i++)
        #pragma unroll
        for (int j = 0; j < 8; j++)
            #pragma unroll
            for (int e = 0; e < 4; e++) acc[i][j][e] = 0.f;

    // staging: each thread owns 4 rows (stride 32) at fixed f4-column (tid&7)
    const int ar[4] = { tid >> 3, (tid + 256) >> 3, (tid + 512) >> 3, (tid + 768) >> 3 };
    const int ac    = tid & 7;
    float4 regA[4]; uint2 regBh[4], regBl[4];

    const int NS = K >> 5;

    auto g2r = [&](int s) {
        const int k0 = s << 5;
        #pragma unroll
        for (int q = 0; q < 4; q++) {
            int row = ar[q];
            regA[q] = (bm + row < M)
                ? *(const float4*)(A + (size_t)(bm + row) * K + k0 + ac * 4)
                : make_float4(0.f, 0.f, 0.f, 0.f);
            size_t boff = (size_t)(bn + row) * K + k0 + ac * 4;
            regBh[q] = *(const uint2*)(Bhi + boff);
            regBl[q] = *(const uint2*)(Blo + boff);
        }
    };
    auto r2s = [&]() {
        #pragma unroll
        for (int q = 0; q < 4; q++) {
            int row = ar[q];
            float4 v = regA[q];
            __nv_bfloat162 h01 = __floats2bfloat162_rn(v.x, v.y);
            __nv_bfloat162 h23 = __floats2bfloat162_rn(v.z, v.w);
            float2 f01 = __bfloat1622float2(h01);
            float2 f23 = __bfloat1622float2(h23);
            __nv_bfloat162 l01 = __floats2bfloat162_rn(v.x - f01.x, v.y - f01.y);
            __nv_bfloat162 l23 = __floats2bfloat162_rn(v.z - f23.x, v.w - f23.y);
            int o = row * ROWU + ac * 2;
            sAh[o]     = *(uint32_t*)&h01;
            sAh[o + 1] = *(uint32_t*)&h23;
            sAl[o]     = *(uint32_t*)&l01;
            sAl[o + 1] = *(uint32_t*)&l23;
            *(uint2*)&sBh[o] = regBh[q];
            *(uint2*)&sBl[o] = regBl[q];
        }
    };

    g2r(0); r2s(); __syncthreads();

    for (int s = 0; s < NS; s++) {
        if (s + 1 < NS) g2r(s + 1);    // prefetch next stage to registers

        #pragma unroll
        for (int kk = 0; kk < 2; kk++) {     // two k16 steps in BK=32
            const int kb = kk * 8 + t;       // u32 col base
            uint32_t ah[2][4], al[2][4];
            #pragma unroll
            for (int i = 0; i < 2; i++) {
                int r0 = (wm + i * 16 + g) * ROWU;
                int r8 = r0 + 8 * ROWU;
                ah[i][0] = sAh[r0 + kb];      ah[i][1] = sAh[r8 + kb];
                ah[i][2] = sAh[r0 + kb + 4];  ah[i][3] = sAh[r8 + kb + 4];
                al[i][0] = sAl[r0 + kb];      al[i][1] = sAl[r8 + kb];
                al[i][2] = sAl[r0 + kb + 4];  al[i][3] = sAl[r8 + kb + 4];
            }
            #pragma unroll
            for (int j = 0; j < 8; j++) {
                int nr = (wn + j * 8 + g) * ROWU;
                uint32_t bh0 = sBh[nr + kb], bh1 = sBh[nr + kb + 4];
                uint32_t bl0 = sBl[nr + kb], bl1 = sBl[nr + kb + 4];
                #pragma unroll
                for (int i = 0; i < 2; i++) {
                    mma16816(acc[i][j], ah[i], bh0, bh1);
                    mma16816(acc[i][j], ah[i], bl0, bl1);
                    mma16816(acc[i][j], al[i], bh0, bh1);
                }
            }
        }

        __syncthreads();               // all reads of this stage done
        if (s + 1 < NS) { r2s(); __syncthreads(); }
    }

    // ---- epilogue ----
    #pragma unroll
    for (int i = 0; i < 2; i++) {
        #pragma unroll
        for (int half = 0; half < 2; half++) {   // c0/c1 (row g) vs c2/c3 (row g+8)
            int row = bm + wm + i * 16 + g + half * 8;
            if (row >= M) continue;
            size_t cr = (size_t)row * N;
            #pragma unroll
            for (int j = 0; j < 8; j++) {
                int col = bn + wn + j * 8 + 2 * t;
                float v0 = acc[i][j][half * 2 + 0];
                float v1 = acc[i][j][half * 2 + 1];
                if (bias) { v0 += __ldg(&bias[col]); v1 += __ldg(&bias[col + 1]); }
                if (RELU) { v0 = fmaxf(v0, 0.f); v1 = fmaxf(v1, 0.f); }
                if (res)  { v0 += res[cr + col]; v1 += res[cr + col + 1]; }
                *(float2*)&C[cr + col] = make_float2(v0, v1);
            }
        }
    }
}

// ---------------- weight prep: transpose fp32 [K,N] -> bf16 hi/lo [N,K] ----------------
__global__ void wprep_kernel(const float* __restrict__ W,
                             __nv_bfloat16* __restrict__ hi,
                             __nv_bfloat16* __restrict__ lo, int K, int N) {
    __shared__ float t[32][33];
    int n0 = blockIdx.x * 32, k0 = blockIdx.y * 32;
    int tx = threadIdx.x, ty0 = threadIdx.y;
    #pragma unroll
    for (int j = 0; j < 32; j += 8) {
        int ty = ty0 + j;
        t[ty][tx] = W[(size_t)(k0 + ty) * N + n0 + tx];
    }
    __syncthreads();
    #pragma unroll
    for (int j = 0; j < 32; j += 8) {
        int ty = ty0 + j;
        float v = t[tx][ty];   // = W[k0+tx][n0+ty]
        __nv_bfloat16 h = __float2bfloat16(v);
        size_t o = (size_t)(n0 + ty) * K + k0 + tx;
        hi[o] = h;
        lo[o] = __float2bfloat16(v - __bfloat162float(h));
    }
}

// split fp32 -> bf16 hi/lo, no transpose
__global__ void wsplit_kernel(const float* __restrict__ W,
                              __nv_bfloat16* __restrict__ hi,
                              __nv_bfloat16* __restrict__ lo, int n) {
    int i = blockIdx.x * blockDim.x + threadIdx.x;
    if (i < n) {
        float v = W[i];
        __nv_bfloat16 h = __float2bfloat16(v);
        hi[i] = h;
        lo[i] = __float2bfloat16(v - __bfloat162float(h));
    }
}

// ---------------- twiddle init ----------------
__global__ void init_tw_kernel() {
    int k = blockIdx.x * blockDim.x + threadIdx.x;
    if (k < Lk/2) {
        double ang = -2.0 * PI_D * (double)k / (double)Lk;
        g_tw[k] = make_float2((float)cos(ang), (float)sin(ang));
    }
}

// ---------------- in-smem iterative radix-2 FFT (input already bit-reversed) ----------------
__device__ __forceinline__ void fft_core(float2* s) {
    for (int len = 2; len <= Lk; len <<= 1) {
        int half = len >> 1;
        int lh   = __ffs(half) - 1;
        int tws  = Lk / len;
        for (int j = threadIdx.x; j < Lk/2; j += blockDim.x) {
            int k  = j & (half - 1);
            int g  = j >> lh;
            int i0 = g * len + k;
            int i1 = i0 + half;
            float2 w = g_tw[k * tws];
            float2 a = s[i0], b = s[i1];
            float tre = w.x * b.x - w.y * b.y;
            float tim = w.x * b.y + w.y * b.x;
            s[i1] = make_float2(a.x - tre, a.y - tim);
            s[i0] = make_float2(a.x + tre, a.y + tim);
        }
        __syncthreads();
    }
}

__global__ void fft_x_kernel(const float* __restrict__ x) {
    __shared__ float2 s[Lk];
    int b  = blockIdx.x;
    int pr = blockIdx.y;
    int d0 = 2 * pr, d1 = d0 + 1;
    const float* xb = x + (size_t)b * Lk * Dk;
    for (int t = threadIdx.x; t < Lk; t += blockDim.x) {
        int r = __brev((unsigned)t) >> (32 - 12);
        s[r] = make_float2(xb[(size_t)t * Dk + d0], xb[(size_t)t * Dk + d1]);
    }
    __syncthreads();
    fft_core(s);
    float* Ure = g_U;
    float* Uim = g_U + (size_t)Bk * NFk * Dk;
    for (int f = threadIdx.x; f <= Lk/2; f += blockDim.x) {
        float2 zf = s[f];
        float2 zn = s[(Lk - f) & (Lk - 1)];
        float are = 0.5f * (zf.x + zn.x);
        float aim = 0.5f * (zf.y - zn.y);
        float bre = 0.5f * (zf.y + zn.y);
        float bim = 0.5f * (zn.x - zf.x);
        size_t row = ((size_t)b * NFk + f) * Dk;
        Ure[row + d0] = are;  Uim[row + d0] = aim;
        Ure[row + d1] = bre;  Uim[row + d1] = bim;
    }
}

// S[b,f] = (U@G)[b,f,:] . conj(U[b,f,:])     (f=0 fixed exactly by s0fix_kernel)
__global__ void sreduce_kernel() {
    int row = blockIdx.x;                // b*NF + f
    const float* vre = g_VU + (size_t)row * Dk;
    const float* vim = g_VU + ((size_t)(Bk*NFk) + row) * Dk;
    const float* ure = g_U  + (size_t)row * Dk;
    const float* uim = g_U  + ((size_t)(Bk*NFk) + row) * Dk;
    float sre = 0.f, sim = 0.f;
    for (int d = threadIdx.x; d < Dk; d += blockDim.x) {
        float vr = vre[d], vi = vim[d], ur = ure[d], ui = uim[d];
        sre += vr * ur + vi * ui;
        sim += vi * ur - vr * ui;
    }
    __shared__ float rre[128], rim[128];
    int tid = threadIdx.x;
    rre[tid] = sre; rim[tid] = sim;
    __syncthreads();
    for (int st = 64; st > 0; st >>= 1) {
        if (tid < st) { rre[tid] += rre[tid + st]; rim[tid] += rim[tid + st]; }
        __syncthreads();
    }
    if (tid == 0) g_S[row] = make_float2(rre[0], rim[0]);
}

// exact fp32 S at f=0 (with bias terms): S0 = (u0@Wq + L*bq) . (u0@Wk + L*bk)
__global__ void s0fix_kernel(const float* __restrict__ Wq, const float* __restrict__ bq,
                             const float* __restrict__ Wk, const float* __restrict__ bk) {
    int b = blockIdx.x;
    int i = threadIdx.x;                 // 512 threads
    __shared__ float u0[Dk];
    const float* ur = g_U + (size_t)(b * NFk) * Dk;
    u0[i] = ur[i];
    __syncthreads();
    float q = 0.f, k = 0.f;
    for (int t = 0; t < Dk; t++) {
        float u = u0[t];
        q += u * Wq[(size_t)t * Dk + i];
        k += u * Wk[(size_t)t * Dk + i];
    }
    q += (float)Lk * bq[i];
    k += (float)Lk * bk[i];
    __shared__ float red[Dk];
    red[i] = q * k;
    __syncthreads();
    for (int st = 256; st > 0; st >>= 1) {
        if (i < st) red[i] += red[i + st];
        __syncthreads();
    }
    if (i == 0) g_S[b * NFk] = make_float2(red[0], 0.f);
}

// mean_corr = irfft(S)/D via conj trick through the forward FFT core.
__global__ void ifft_corr_kernel() {
    __shared__ float2 s[Lk];
    int b = blockIdx.x;
    for (int f = threadIdx.x; f < Lk; f += blockDim.x) {
        float2 v;
        if (f <= Lk/2) { float2 sf = g_S[b * NFk + f]; v = make_float2(sf.x, -sf.y); }
        else           { v = g_S[b * NFk + (Lk - f)]; }
        int r = __brev((unsigned)f) >> (32 - 12);
        s[r] = v;
    }
    __syncthreads();
    fft_core(s);
    float scale = 1.0f / ((float)Lk * (float)Dk);
    for (int t = threadIdx.x; t < Lk; t += blockDim.x)
        g_corr[b * Lk + t] = s[t].x * scale;
}

// top-8 (stable, descending, lower-index wins ties) + softmax
__global__ void topk_kernel() {
    int b = blockIdx.x;
    const float* c = g_corr + b * Lk;
    __shared__ float sv[256];
    __shared__ int   si[256];
    __shared__ int   ch_i[KTOP];
    __shared__ float ch_v[KTOP];
    int tid = threadIdx.x;
    for (int it = 0; it < KTOP; it++) {
        float bv = -3.402823e38f; int bi = 0x7fffffff;
        for (int t = tid; t < Lk; t += 256) {
            bool skip = false;
            for (int q = 0; q < it; q++) if (ch_i[q] == t) skip = true;
            if (skip) continue;
            float v = c[t];
            if (v > bv || (v == bv && t < bi)) { bv = v; bi = t; }
        }
        sv[tid] = bv; si[tid] = bi;
        __syncthreads();
        for (int st = 128; st > 0; st >>= 1) {
            if (tid < st) {
                if (sv[tid+st] > sv[tid] || (sv[tid+st] == sv[tid] && si[tid+st] < si[tid])) {
                    sv[tid] = sv[tid+st]; si[tid] = si[tid+st];
                }
            }
            __syncthreads();
        }
        if (tid == 0) { ch_i[it] = si[0]; ch_v[it] = sv[0]; }
        __syncthreads();
    }
    if (tid == 0) {
        float m = ch_v[0];
        for (int q = 1; q < KTOP; q++) m = fmaxf(m, ch_v[q]);
        float e[KTOP]; float sum = 0.f;
        for (int q = 0; q < KTOP; q++) { e[q] = expf(ch_v[q] - m); sum += e[q]; }
        for (int q = 0; q < KTOP; q++) {
            g_p[b*KTOP+q]     = e[q] / sum;
            g_delay[b*KTOP+q] = ch_i[q];
        }
    }
}

// attn[b,t,:] = sum_j p_j * V[b,(t+delay_j)%L,:]
__global__ void gather_kernel() {
    int bt = blockIdx.x;
    int b = bt >> 12, t = bt & (Lk - 1);
    __shared__ float pp[KTOP];
    __shared__ int   dd[KTOP];
    if (threadIdx.x < KTOP) {
        pp[threadIdx.x] = g_p[b*KTOP + threadIdx.x];
        dd[threadIdx.x] = g_delay[b*KTOP + threadIdx.x];
    }
    __syncthreads();
    int d = threadIdx.x * 4;
    float4 acc = make_float4(0.f, 0.f, 0.f, 0.f);
    #pragma unroll
    for (int j = 0; j < KTOP; j++) {
        int src = (t + dd[j]) & (Lk - 1);
        float4 v = *(const float4*)&g_V[(((size_t)b * Lk) + src) * Dk + d];
        acc.x += pp[j] * v.x; acc.y += pp[j] * v.y;
        acc.z += pp[j] * v.z; acc.w += pp[j] * v.w;
    }
    *(float4*)&g_attn[(size_t)bt * Dk + d] = acc;
}

// out = h - avgpool_same(h, 25)
__global__ void pool_kernel(const float* __restrict__ h, float* __restrict__ out) {
    int b  = blockIdx.y;
    int t0 = blockIdx.x * 512;
    int d  = threadIdx.x;
    const float* hb = h   + (size_t)b * Lk * Dk + d;
    float*       ob = out + (size_t)b * Lk * Dk + d;
    float sum = 0.f;
    int lo = t0 - 12 < 0 ? 0 : t0 - 12;
    int hi = t0 + 12 > Lk - 1 ? Lk - 1 : t0 + 12;
    for (int t = lo; t <= hi; t++) sum += hb[(size_t)t * Dk];
    for (int t = t0; t < t0 + 512; t++) {
        int wlo = t - 12 < 0 ? 0 : t - 12;
        int whi = t + 12 > Lk - 1 ? Lk - 1 : t + 12;
        float cnt = (float)(whi - wlo + 1);
        ob[(size_t)t * Dk] = hb[(size_t)t * Dk] - sum / cnt;
        int add = t + 13; if (add < Lk)  sum += hb[(size_t)add * Dk];
        int rem = t - 12; if (rem >= 0)  sum -= hb[(size_t)rem * Dk];
    }
}

// ---------------- launch ----------------
extern "C" void kernel_launch(void* const* d_in, const int* in_sizes, int n_in,
                              void* d_out, int out_size) {
    const float* x  = (const float*)d_in[0];
    const float* Wq = (const float*)d_in[1];
    const float* bq = (const float*)d_in[2];
    const float* Wk = (const float*)d_in[3];
    const float* bk = (const float*)d_in[4];
    const float* Wv = (const float*)d_in[5];
    const float* bv = (const float*)d_in[6];
    const float* Wo = (const float*)d_in[7];
    const float* bo = (const float*)d_in[8];
    const float* W1 = (const float*)d_in[9];
    const float* b1 = (const float*)d_in[10];
    const float* W2 = (const float*)d_in[11];
    const float* b2 = (const float*)d_in[12];
    float* out = (float*)d_out;

    float *pV, *pU, *pVU, *pattn, *ph, *pS1, *phid, *ph2, *pG;
    __nv_bfloat16 *pWvt_h,*pWvt_l,*pWot_h,*pWot_l,*pW1t_h,*pW1t_l,*pW2t_h,*pW2t_l,*pWk_h,*pWk_l,*pGt_h,*pGt_l;
    cudaGetSymbolAddress((void**)&pV,    g_V);
    cudaGetSymbolAddress((void**)&pU,    g_U);
    cudaGetSymbolAddress((void**)&pVU,   g_VU);
    cudaGetSymbolAddress((void**)&pattn, g_attn);
    cudaGetSymbolAddress((void**)&ph,    g_h);
    cudaGetSymbolAddress((void**)&pS1,   g_S1);
    cudaGetSymbolAddress((void**)&phid,  g_hid);
    cudaGetSymbolAddress((void**)&ph2,   g_h2);
    cudaGetSymbolAddress((void**)&pG,    g_G);
    cudaGetSymbolAddress((void**)&pWvt_h, g_Wvt_h); cudaGetSymbolAddress((void**)&pWvt_l, g_Wvt_l);
    cudaGetSymbolAddress((void**)&pWot_h, g_Wot_h); cudaGetSymbolAddress((void**)&pWot_l, g_Wot_l);
    cudaGetSymbolAddress((void**)&pW1t_h, g_W1t_h); cudaGetSymbolAddress((void**)&pW1t_l, g_W1t_l);
    cudaGetSymbolAddress((void**)&pW2t_h, g_W2t_h); cudaGetSymbolAddress((void**)&pW2t_l, g_W2t_l);
    cudaGetSymbolAddress((void**)&pWk_h,  g_Wk_h);  cudaGetSymbolAddress((void**)&pWk_l,  g_Wk_l);
    cudaGetSymbolAddress((void**)&pGt_h,  g_Gt_h);  cudaGetSymbolAddress((void**)&pGt_l,  g_Gt_l);

    const int MR = Bk * Lk;              // 16384
    const int MU = 2 * Bk * NFk;         // 16392
    const int MUt = (MU + 127) / 128;    // 129

    init_tw_kernel<<<(Lk/2 + 255)/256, 256>>>();

    // weight prep
    dim3 wb(32, 8);
    wprep_kernel<<<dim3(Dk/32,  Dk/32),  wb>>>(Wv, pWvt_h, pWvt_l, Dk, Dk);
    wprep_kernel<<<dim3(Dk/32,  Dk/32),  wb>>>(Wo, pWot_h, pWot_l, Dk, Dk);
    wprep_kernel<<<dim3(DFFk/32, Dk/32), wb>>>(W1, pW1t_h, pW1t_l, Dk, DFFk);
    wprep_kernel<<<dim3(Dk/32,  DFFk/32),wb>>>(W2, pW2t_h, pW2t_l, DFFk, Dk);
    wsplit_kernel<<<(Dk*Dk + 255)/256, 256>>>(Wk, pWk_h, pWk_l, Dk*Dk);

    // G = Wq @ Wk^T  (512x512x512)
    mmgemm_kernel<false><<<dim3(Dk/128, Dk/128), 256>>>(
        Wq, pWk_h, pWk_l, nullptr, nullptr, pG, Dk, Dk, Dk);
    wprep_kernel<<<dim3(Dk/32, Dk/32), wb>>>(pG, pGt_h, pGt_l, Dk, Dk);

    // spectrum of x
    fft_x_kernel<<<dim3(Bk, Dk/2), 512>>>(x);

    // V = x@Wv + bv
    mmgemm_kernel<false><<<dim3(Dk/128, MR/128), 256>>>(
        x, pWvt_h, pWvt_l, bv, nullptr, pV, MR, Dk, Dk);

    // VU = U@G
    mmgemm_kernel<false><<<dim3(Dk/128, MUt), 256>>>(
        pU, pGt_h, pGt_l, nullptr, nullptr, pVU, MU, Dk, Dk);

    // S, exact f=0, mean_corr, top-k, gather
    sreduce_kernel<<<Bk * NFk, 128>>>();
    s0fix_kernel<<<Bk, Dk>>>(Wq, bq, Wk, bk);
    ifft_corr_kernel<<<Bk, 512>>>();
    topk_kernel<<<Bk, 256>>>();
    gather_kernel<<<Bk * Lk, 128>>>();

    // h = attn@Wo + bo + x
    mmgemm_kernel<false><<<dim3(Dk/128, MR/128), 256>>>(
        pattn, pWot_h, pWot_l, bo, x, ph, MR, Dk, Dk);

    // S1 = h - avgpool(h)
    pool_kernel<<<dim3(Lk/512, Bk), 512>>>(ph, pS1);

    // hidden = relu(S1@W1 + b1)
    mmgemm_kernel<true><<<dim3(DFFk/128, MR/128), 256>>>(
        pS1, pW1t_h, pW1t_l, b1, nullptr, phid, MR, DFFk, Dk);

    // h2 = relu(hidden@W2 + b2) + S1
    mmgemm_kernel<true><<<dim3(Dk/128, MR/128), 256>>>(
        phid, pW2t_h, pW2t_l, b2, pS1, ph2, MR, Dk, DFFk);

    // out = h2 - avgpool(h2)
    pool_kernel<<<dim3(Lk/512, Bk), 512>>>(ph2, out);
}